// round 13
// baseline (speedup 1.0000x reference)
#include <cuda_runtime.h>

// SSIM loss, single fused kernel, f32x2-packed blurs, GMEM-direct 8-wide streamed
// horizontal pass, interleaved moments, 12-long vertical runs, 3 CTAs/SM.
// Shapes fixed: (16,31,256,256) fp32 x2 inputs, scalar fp32 out.

#define IMG   256
#define OUT   246          // 256 - 11 + 1
#define TW    32
#define TH    82           // output rows per block (3 blocks cover 246)
#define HALO  10
#define IN_H  92           // TH + HALO
#define ROWSA 94           // smem rows allocated (g=6 window reaches row 93)
#define PADI  33           // row stride (ulonglong2 elems) for interleaved moments
#define PADH  36           // row stride (floats) for hm4
#define NIMG  496
#define GX    8
#define GY    3
#define NBLOCKS (GX * GY * NIMG)   // 11904
#define NTOT  30015936.0   // 496 * 246 * 246

#define HMI_B  (ROWSA * PADI * 16)           // 49632
#define HM4_B  (ROWSA * PADH * 4)            // 13536
#define SMEM_B (HMI_B + HM4_B)               // 63168  (x3 CTAs = 189.5 kB)

typedef unsigned long long u64;

__device__ constexpr float GW[11] = {
    0.00102838f, 0.00759874f, 0.03600078f, 0.10936071f, 0.21300555f,
    0.26601174f,
    0.21300555f, 0.10936071f, 0.03600078f, 0.00759874f, 0.00102838f
};

#define C1 1.0e-4f
#define C2 9.0e-4f

// ---- packed f32x2 helpers ----
__device__ __forceinline__ u64 pk2(float x, float y) {
    u64 r; asm("mov.b64 %0, {%1, %2};" : "=l"(r) : "f"(x), "f"(y)); return r;
}
__device__ __forceinline__ void unpk(u64 p, float& x, float& y) {
    asm("mov.b64 {%0, %1}, %2;" : "=f"(x), "=f"(y) : "l"(p));
}
__device__ __forceinline__ u64 f2fma(u64 a, u64 b, u64 c) {
    u64 d; asm("fma.rn.f32x2 %0, %1, %2, %3;" : "=l"(d) : "l"(a), "l"(b), "l"(c)); return d;
}
__device__ __forceinline__ u64 f2mul(u64 a, u64 b) {
    u64 d; asm("mul.rn.f32x2 %0, %1, %2;" : "=l"(d) : "l"(a), "l"(b)); return d;
}

__device__ double   g_acc;      // zero-init; each call leaves it back at 0
__device__ unsigned g_ticket;   // wraps back to 0 every call

// 8-output horizontal run, streamed in 5 float4 chunks (taps k=0..17).
// Live state: A[8]+B[8]+S[8] = 40 regs + one chunk pair (8) + weights (12).
template<bool FAST>
__device__ __forceinline__ void hrun8(const float* __restrict__ xr,
                                      const float* __restrict__ yr,
                                      int gc, bool row_ok,
                                      u64* __restrict__ A, u64* __restrict__ B,
                                      float* __restrict__ S,
                                      const u64* __restrict__ W2h) {
    #pragma unroll
    for (int j = 0; j < 8; j++) { A[j] = 0; B[j] = 0; S[j] = 0.f; }

    #pragma unroll
    for (int q = 0; q < 5; q++) {
        float4 x4, y4;
        if (FAST) {
            if (row_ok) {
                x4 = *(const float4*)(xr + 4 * q);
                y4 = *(const float4*)(yr + 4 * q);
            } else {
                x4 = make_float4(0.f, 0.f, 0.f, 0.f);
                y4 = make_float4(0.f, 0.f, 0.f, 0.f);
            }
        } else {
            float xt[4], yt[4];
            #pragma unroll
            for (int t = 0; t < 4; t++) {
                bool ok = row_ok && (gc + 4 * q + t < IMG);
                xt[t] = ok ? xr[4 * q + t] : 0.f;
                yt[t] = ok ? yr[4 * q + t] : 0.f;
            }
            x4 = make_float4(xt[0], xt[1], xt[2], xt[3]);
            y4 = make_float4(yt[0], yt[1], yt[2], yt[3]);
        }
        const float* xs = &x4.x;
        const float* ys = &y4.x;
        #pragma unroll
        for (int t = 0; t < 4; t++) {
            const int k = 4 * q + t;
            if (k >= 18) continue;               // static prune (k=18,19 unused)
            float xk = xs[t], yk = ys[t];
            u64   p  = pk2(xk, yk);
            u64   sq = f2mul(p, p);
            float xy = xk * yk;
            #pragma unroll
            for (int j = 0; j < 8; j++) {
                const int kj = k - j;
                if (kj >= 0 && kj <= 10) {
                    const int wi = (kj <= 5) ? kj : 10 - kj;   // symmetry
                    A[j] = f2fma(p,  W2h[wi], A[j]);
                    B[j] = f2fma(sq, W2h[wi], B[j]);
                    S[j] = fmaf(GW[kj], xy, S[j]);             // imm-FFMA
                }
            }
        }
    }
}

__global__ __launch_bounds__(256, 3)
void ssim_main_kernel(const float* __restrict__ X, const float* __restrict__ Y,
                      float* __restrict__ out) {
    extern __shared__ __align__(16) unsigned char dsm[];
    ulonglong2 (*hmi)[PADI] = (ulonglong2(*)[PADI]) dsm;          // {.x={hx,hy}, .y={hxx,hyy}}
    float      (*hm4)[PADH] = (float     (*)[PADH])(dsm + HMI_B); // hxy
    __shared__ float red[8];

    const int tid = threadIdx.x;
    const int C0  = blockIdx.x * TW;
    const int R0  = blockIdx.y * TH;
    const int img = blockIdx.z;

    const float* __restrict__ xi = X + (size_t)img * IMG * IMG;
    const float* __restrict__ yi = Y + (size_t)img * IMG * IMG;

    // 6 distinct packed weight pairs (Gaussian symmetry: GW[k] == GW[10-k])
    u64 W2h[6];
    #pragma unroll
    for (int k = 0; k < 6; k++) W2h[k] = pk2(GW[k], GW[k]);

    // ---- Phase 1: horizontal blur from GMEM. 92 rows x 4 runs of 8 outputs = 368.
    const bool fastcol = (C0 + 41 < IMG);   // max col read = C0 + 24 + 17
    for (int i = tid; i < IN_H * 4; i += 256) {
        const int r  = i >> 2;
        const int c0 = (i & 3) * 8;
        const int gr = R0 + r;               // R0<=164, r<=91 -> gr<=255, always valid
        const int gc = C0 + c0;              // multiple of 4 -> 16B aligned
        const bool row_ok = (gr < IMG);
        const float* xr = xi + gr * IMG + gc;
        const float* yr = yi + gr * IMG + gc;

        u64 A[8], B[8]; float S[8];
        if (fastcol) hrun8<true >(xr, yr, gc, row_ok, A, B, S, W2h);
        else         hrun8<false>(xr, yr, gc, row_ok, A, B, S, W2h);

        #pragma unroll
        for (int j = 0; j < 8; j++)
            hmi[r][c0 + j] = make_ulonglong2(A[j], B[j]);
        *(float4*)&hm4[r][c0]     = make_float4(S[0], S[1], S[2], S[3]);
        *(float4*)&hm4[r][c0 + 4] = make_float4(S[4], S[5], S[6], S[7]);
    }
    __syncthreads();

    // ---- Phase 2: vertical blur (streaming, 12-output runs, 7 groups) + SSIM.
    const int c = tid & 31;
    const int g = tid >> 5;

    float lsum = 0.f;
    if (g < 7) {
        const int r0 = g * 12;               // 0..72; window rows r0..r0+21 <= 93 < ROWSA

        u64 acc01[12], acc23[12];
        #pragma unroll
        for (int j = 0; j < 12; j++) { acc01[j] = 0; acc23[j] = 0; }

        #pragma unroll
        for (int k = 0; k < 22; k++) {
            ulonglong2 v = hmi[r0 + k][c];   // one LDS.128 feeds both moment pairs
            #pragma unroll
            for (int j = 0; j < 12; j++) {
                const int kj = k - j;
                if (kj >= 0 && kj <= 10) {
                    const int wi = (kj <= 5) ? kj : 10 - kj;
                    acc01[j] = f2fma(v.x, W2h[wi], acc01[j]);
                    acc23[j] = f2fma(v.y, W2h[wi], acc23[j]);
                }
            }
        }

        float acc4[12];
        #pragma unroll
        for (int j = 0; j < 12; j++) acc4[j] = 0.f;
        #pragma unroll
        for (int k = 0; k < 22; k++) {
            float v = hm4[r0 + k][c];
            #pragma unroll
            for (int j = 0; j < 12; j++) {
                const int kj = k - j;
                if (kj >= 0 && kj <= 10) acc4[j] = fmaf(GW[kj], v, acc4[j]);  // imm-FFMA
            }
        }

        const int oc = C0 + c;
        #pragma unroll
        for (int j = 0; j < 12; j++) {
            if (r0 + j < TH && oc < OUT) {   // R0+TH-1 <= 245, so orow<OUT implied
                float mx, my;   unpk(acc01[j], mx, my);
                float mxx, myy; unpk(acc23[j], mxx, myy);
                float mxy = acc4[j];
                float vx  = mxx - mx * mx;
                float vy  = myy - my * my;
                float cov = mxy - mx * my;
                float num = (2.f * mx * my + C1) * (2.f * cov + C2);
                float den = (mx * mx + my * my + C1) * (vx + vy + C2);
                lsum += __fdividef(num, den);
            }
        }
    }

    // ---- block reduce -> global accumulator; last block finalizes + resets
    #pragma unroll
    for (int o = 16; o > 0; o >>= 1)
        lsum += __shfl_xor_sync(0xffffffffu, lsum, o);
    if ((tid & 31) == 0) red[tid >> 5] = lsum;
    __syncthreads();
    if (tid == 0) {
        float s = 0.f;
        #pragma unroll
        for (int w = 0; w < 8; w++) s += red[w];
        atomicAdd(&g_acc, (double)s);
        __threadfence();
        unsigned t = atomicInc(&g_ticket, NBLOCKS - 1);
        if (t == NBLOCKS - 1) {
            double tot = atomicAdd(&g_acc, 0.0);   // coherent read
            out[0] = (float)(1.0 - tot / NTOT);
            atomicExch((unsigned long long*)&g_acc, 0ull);  // reset for next call
        }
    }
}

extern "C" void kernel_launch(void* const* d_in, const int* in_sizes, int n_in,
                              void* d_out, int out_size) {
    const float* X = (const float*)d_in[0];
    const float* Y = (const float*)d_in[1];
    float* out = (float*)d_out;

    cudaFuncSetAttribute(ssim_main_kernel,
                         cudaFuncAttributeMaxDynamicSharedMemorySize, SMEM_B);

    dim3 grid(GX, GY, NIMG);   // 8 x 3 x 496
    ssim_main_kernel<<<grid, 256, SMEM_B>>>(X, Y, out);
}

// round 14
// speedup vs baseline: 1.2271x; 1.2271x over previous
#include <cuda_runtime.h>

// SSIM loss, single fused kernel. 4-moment formulation: blur {x,y} and {x^2+y^2, x*y}
// as two packed f32x2 channels. GMEM-direct streamed horizontal pass, interleaved
// moment smem, 8-long vertical runs, 4 CTAs/SM.
// Shapes fixed: (16,31,256,256) fp32 x2 inputs, scalar fp32 out.

#define IMG   256
#define OUT   246          // 256 - 11 + 1
#define TW    32
#define TH    64
#define HALO  10
#define IN_H  74           // TH + HALO
#define PADI  33           // row stride (ulonglong2 elems) for interleaved moments
#define NIMG  496
#define GX    8
#define GY    4
#define NBLOCKS (GX * GY * NIMG)   // 15872
#define NTOT  30015936.0   // 496 * 246 * 246

#define SMEM_B (IN_H * PADI * 16)            // 39072  (x4 CTAs = 156 kB)

typedef unsigned long long u64;

__device__ constexpr float GW[11] = {
    0.00102838f, 0.00759874f, 0.03600078f, 0.10936071f, 0.21300555f,
    0.26601174f,
    0.21300555f, 0.10936071f, 0.03600078f, 0.00759874f, 0.00102838f
};

#define C1 1.0e-4f
#define C2 9.0e-4f

// ---- packed f32x2 helpers ----
__device__ __forceinline__ u64 pk2(float x, float y) {
    u64 r; asm("mov.b64 %0, {%1, %2};" : "=l"(r) : "f"(x), "f"(y)); return r;
}
__device__ __forceinline__ void unpk(u64 p, float& x, float& y) {
    asm("mov.b64 {%0, %1}, %2;" : "=f"(x), "=f"(y) : "l"(p));
}
__device__ __forceinline__ u64 f2fma(u64 a, u64 b, u64 c) {
    u64 d; asm("fma.rn.f32x2 %0, %1, %2, %3;" : "=l"(d) : "l"(a), "l"(b), "l"(c)); return d;
}

__device__ double   g_acc;      // zero-init; each call leaves it back at 0
__device__ unsigned g_ticket;   // wraps back to 0 every call

// 4-output horizontal run, streamed in 4 float4 chunks (taps k=0..13).
// Channels: p={x,y}, q={x^2+y^2, x*y}. Live: A[4]+Q[4]=16 regs + chunk(8) + weights(12).
template<bool FAST>
__device__ __forceinline__ void hrun4(const float* __restrict__ xr,
                                      const float* __restrict__ yr,
                                      int gc, bool row_ok,
                                      u64* __restrict__ A, u64* __restrict__ Q,
                                      const u64* __restrict__ W2h) {
    #pragma unroll
    for (int j = 0; j < 4; j++) { A[j] = 0; Q[j] = 0; }

    #pragma unroll
    for (int q = 0; q < 4; q++) {
        float4 x4, y4;
        if (FAST) {
            if (row_ok) {
                x4 = *(const float4*)(xr + 4 * q);
                y4 = *(const float4*)(yr + 4 * q);
            } else {
                x4 = make_float4(0.f, 0.f, 0.f, 0.f);
                y4 = make_float4(0.f, 0.f, 0.f, 0.f);
            }
        } else {
            float xt[4], yt[4];
            #pragma unroll
            for (int t = 0; t < 4; t++) {
                bool ok = row_ok && (gc + 4 * q + t < IMG);
                xt[t] = ok ? xr[4 * q + t] : 0.f;
                yt[t] = ok ? yr[4 * q + t] : 0.f;
            }
            x4 = make_float4(xt[0], xt[1], xt[2], xt[3]);
            y4 = make_float4(yt[0], yt[1], yt[2], yt[3]);
        }
        const float* xs = &x4.x;
        const float* ys = &y4.x;
        #pragma unroll
        for (int t = 0; t < 4; t++) {
            const int k = 4 * q + t;
            if (k >= 14) continue;               // static prune
            float xk = xs[t], yk = ys[t];
            u64   p  = pk2(xk, yk);
            float ss = fmaf(yk, yk, xk * xk);    // x^2 + y^2
            float xy = xk * yk;
            u64   qv = pk2(ss, xy);
            #pragma unroll
            for (int j = 0; j < 4; j++) {
                const int kj = k - j;
                if (kj >= 0 && kj <= 10) {
                    const int wi = (kj <= 5) ? kj : 10 - kj;   // symmetry
                    A[j] = f2fma(p,  W2h[wi], A[j]);
                    Q[j] = f2fma(qv, W2h[wi], Q[j]);
                }
            }
        }
    }
}

__global__ __launch_bounds__(256, 4)
void ssim_main_kernel(const float* __restrict__ X, const float* __restrict__ Y,
                      float* __restrict__ out) {
    extern __shared__ __align__(16) unsigned char dsm[];
    ulonglong2 (*hmi)[PADI] = (ulonglong2(*)[PADI]) dsm;  // {.x={hx,hy}, .y={hss,hxy}}
    __shared__ float red[8];

    const int tid = threadIdx.x;
    const int C0  = blockIdx.x * TW;
    const int R0  = blockIdx.y * TH;
    const int img = blockIdx.z;

    const float* __restrict__ xi = X + (size_t)img * IMG * IMG;
    const float* __restrict__ yi = Y + (size_t)img * IMG * IMG;

    // 6 distinct packed weight pairs (Gaussian symmetry: GW[k] == GW[10-k])
    u64 W2h[6];
    #pragma unroll
    for (int k = 0; k < 6; k++) W2h[k] = pk2(GW[k], GW[k]);

    // ---- Phase 1: horizontal blur from GMEM. 74 rows x 8 runs of 4 outputs.
    const bool fastcol = (C0 + 43 < IMG);    // max col read = C0 + 28 + 13 (conservative)
    for (int i = tid; i < IN_H * 8; i += 256) {
        const int r  = i >> 3;
        const int c0 = (i & 7) * 4;
        const int gr = R0 + r;
        const int gc = C0 + c0;              // multiple of 4 -> 16B aligned
        const bool row_ok = (gr < IMG);
        const float* xr = xi + gr * IMG + gc;
        const float* yr = yi + gr * IMG + gc;

        u64 A[4], Q[4];
        if (fastcol) hrun4<true >(xr, yr, gc, row_ok, A, Q, W2h);
        else         hrun4<false>(xr, yr, gc, row_ok, A, Q, W2h);

        #pragma unroll
        for (int j = 0; j < 4; j++)
            hmi[r][c0 + j] = make_ulonglong2(A[j], Q[j]);
    }
    __syncthreads();

    // ---- Phase 2: vertical blur (streaming, 8-output runs) + SSIM.
    const int c  = tid & 31;
    const int r0 = (tid >> 5) * 8;   // 0..56

    u64 acc01[8], accq[8];
    #pragma unroll
    for (int j = 0; j < 8; j++) { acc01[j] = 0; accq[j] = 0; }

    #pragma unroll
    for (int k = 0; k < 18; k++) {
        ulonglong2 v = hmi[r0 + k][c];   // one LDS.128 feeds both packed channels
        #pragma unroll
        for (int j = 0; j < 8; j++) {
            const int kj = k - j;
            if (kj >= 0 && kj <= 10) {
                const int wi = (kj <= 5) ? kj : 10 - kj;
                acc01[j] = f2fma(v.x, W2h[wi], acc01[j]);
                accq[j]  = f2fma(v.y, W2h[wi], accq[j]);
            }
        }
    }

    float lsum = 0.f;
    const int oc = C0 + c;
    #pragma unroll
    for (int j = 0; j < 8; j++) {
        int orow = R0 + r0 + j;
        if (orow < OUT && oc < OUT) {
            float mx, my;   unpk(acc01[j], mx, my);
            float mss, mxy; unpk(accq[j],  mss, mxy);
            float mxmy = mx * my;
            float m2   = fmaf(mx, mx, my * my);          // mx^2 + my^2
            float vsum = mss - m2;                       // vx + vy
            float cov  = mxy - mxmy;
            float num  = (2.f * mxmy + C1) * (2.f * cov + C2);
            float den  = (m2 + C1) * (vsum + C2);
            lsum += __fdividef(num, den);
        }
    }

    // ---- block reduce -> global accumulator; last block finalizes + resets
    #pragma unroll
    for (int o = 16; o > 0; o >>= 1)
        lsum += __shfl_xor_sync(0xffffffffu, lsum, o);
    if ((tid & 31) == 0) red[tid >> 5] = lsum;
    __syncthreads();
    if (tid == 0) {
        float s = 0.f;
        #pragma unroll
        for (int w = 0; w < 8; w++) s += red[w];
        atomicAdd(&g_acc, (double)s);
        __threadfence();
        unsigned t = atomicInc(&g_ticket, NBLOCKS - 1);
        if (t == NBLOCKS - 1) {
            double tot = atomicAdd(&g_acc, 0.0);   // coherent read
            out[0] = (float)(1.0 - tot / NTOT);
            atomicExch((unsigned long long*)&g_acc, 0ull);  // reset for next call
        }
    }
}

extern "C" void kernel_launch(void* const* d_in, const int* in_sizes, int n_in,
                              void* d_out, int out_size) {
    const float* X = (const float*)d_in[0];
    const float* Y = (const float*)d_in[1];
    float* out = (float*)d_out;

    cudaFuncSetAttribute(ssim_main_kernel,
                         cudaFuncAttributeMaxDynamicSharedMemorySize, SMEM_B);

    dim3 grid(GX, GY, NIMG);   // 8 x 4 x 496
    ssim_main_kernel<<<grid, 256, SMEM_B>>>(X, Y, out);
}